// round 5
// baseline (speedup 1.0000x reference)
#include <cuda_runtime.h>
#include <cstdint>

// NAIS scoring via warp-level tf32 mma.sync, software-pipelined A loads.
//
//   qp[d]  = bias[h,d] + sum_e Q[b,h,e] * Wc[h,e,d]            (fp32, exact)
//   out[k] = sum_d relu( qp[d] + (K[k,:] @ Wk)[d] ) * Wo[h,d]  (K@Wk in tf32)
//
// m16n8k8 fragment layouts (g = lane>>2, c = lane&3):
//   A: a0=(g, s0) a1=(g+8, s0) a2=(g, s1) a3=(g+8, s1)
//   B: b0=(k s0, n=g) b1=(k s1, n=g)
//   C: c0=(g,2c) c1=(g,2c+1) c2=(g+8,2c) c3=(g+8,2c+1)
// k-slot -> physical column permutation (same for A and B, step s):
//   (c, slot0) -> 16c+2s, (c, slot1) -> 16c+2s+1   (bijective per step)
//
// Pipeline: each warp processes 16-row tiles; while tile t computes
// (cvt + 64 mma + epilogue), tile t+1's 8 LDG.128 are in flight into the
// other register buffer -> loads-outstanding duty ~100% (was ~50%).

namespace {
constexpr int Bc = 32, Hc = 8, KL = 8192, Dd = 64;
constexpr int NTHREADS = 256;                 // 8 warps
constexpr int KCHUNK   = 1024;                // rows per block
constexpr int ROWS_PER_WARP = KCHUNK / 8;     // 128
constexpr int TILE_ROWS = 16;
constexpr int NTILE     = ROWS_PER_WARP / TILE_ROWS;  // 8
}

__device__ __forceinline__ uint32_t f2tf(float f) {
    uint32_t r;
    asm("cvt.rna.tf32.f32 %0, %1;" : "=r"(r) : "f"(f));
    return r;
}

__device__ __forceinline__ void mma_tf32(float c[4],
                                         uint32_t a0, uint32_t a1, uint32_t a2, uint32_t a3,
                                         uint32_t b0, uint32_t b1) {
    asm volatile(
        "mma.sync.aligned.m16n8k8.row.col.f32.tf32.tf32.f32 "
        "{%0,%1,%2,%3}, {%4,%5,%6,%7}, {%8,%9}, {%0,%1,%2,%3};"
        : "+f"(c[0]), "+f"(c[1]), "+f"(c[2]), "+f"(c[3])
        : "r"(a0), "r"(a1), "r"(a2), "r"(a3), "r"(b0), "r"(b1));
}

// load one 16-row tile's A fragments (raw fp32 bits; cvt happens at compute time)
__device__ __forceinline__ void load_tile(uint32_t buf[2][16],
                                          const float* __restrict__ Kc,
                                          int rowbase, int g, int c) {
    #pragma unroll
    for (int hf = 0; hf < 2; hf++) {
        const int r = rowbase + hf * 8 + g;
        const float4* p = reinterpret_cast<const float4*>(Kc + (size_t)r * Dd + 16 * c);
        float4 f0 = p[0], f1 = p[1], f2 = p[2], f3 = p[3];
        buf[hf][0]  = __float_as_uint(f0.x); buf[hf][1]  = __float_as_uint(f0.y);
        buf[hf][2]  = __float_as_uint(f0.z); buf[hf][3]  = __float_as_uint(f0.w);
        buf[hf][4]  = __float_as_uint(f1.x); buf[hf][5]  = __float_as_uint(f1.y);
        buf[hf][6]  = __float_as_uint(f1.z); buf[hf][7]  = __float_as_uint(f1.w);
        buf[hf][8]  = __float_as_uint(f2.x); buf[hf][9]  = __float_as_uint(f2.y);
        buf[hf][10] = __float_as_uint(f2.z); buf[hf][11] = __float_as_uint(f2.w);
        buf[hf][12] = __float_as_uint(f3.x); buf[hf][13] = __float_as_uint(f3.y);
        buf[hf][14] = __float_as_uint(f3.z); buf[hf][15] = __float_as_uint(f3.w);
    }
}

__global__ void __launch_bounds__(NTHREADS, 2)
nais_mma_kernel(const float* __restrict__ Q, const float* __restrict__ K,
                const float* __restrict__ Wc, const float* __restrict__ Wo,
                const float* __restrict__ bias, float* __restrict__ out)
{
    // B fragments pre-packed: Bp[(nt*8 + s)*32 + lane] =
    //   { tf32 Wk[16c+2s][n], tf32 Wk[16c+2s+1][n] },  n = nt*8 + g
    __shared__ uint2 Bp[8 * 8 * 32];          // 16 KB
    __shared__ float qps[Dd], wos[Dd];

    const int tid  = threadIdx.x;
    const int w    = tid >> 5;
    const int lane = tid & 31;
    const int c    = lane & 3;                // threadID_in_group
    const int g    = lane >> 2;               // groupID

    const int bid   = blockIdx.x;
    const int bh    = bid >> 3;               // b*H + h
    const int chunk = bid & 7;
    const int h     = bh & (Hc - 1);

    const float* __restrict__ WcH = Wc + (size_t)h * 2 * Dd * Dd;
    const float* __restrict__ Wk  = WcH + Dd * Dd;    // bottom half: [e][d]
    const float* __restrict__ Kc  = K + (size_t)bh * KL * Dd + (size_t)chunk * KCHUNK * Dd;
    float* __restrict__ outp = out + (size_t)bh * KL + (size_t)chunk * KCHUNK;

    // ---- prologue ----
    #pragma unroll
    for (int i = 0; i < (8 * 8 * 32) / NTHREADS; i++) {   // 8 packs/thread
        int idx = tid + i * NTHREADS;          // ((nt*8 + s)*32 + ln)
        int ln = idx & 31, s = (idx >> 5) & 7, nt = idx >> 8;
        int cc = ln & 3, gg = ln >> 2;
        int e0 = 16 * cc + 2 * s;
        int n  = nt * 8 + gg;
        Bp[idx] = make_uint2(f2tf(Wk[e0 * Dd + n]), f2tf(Wk[(e0 + 1) * Dd + n]));
    }
    if (tid < Dd) {                            // qp = bias + Q @ Wq (fp32 exact); wo
        wos[tid] = Wo[h * Dd + tid];
        float acc = bias[h * Dd + tid];
        const float* __restrict__ q = Q + (size_t)bh * Dd;
        #pragma unroll 8
        for (int e = 0; e < Dd; e++) acc = fmaf(q[e], WcH[e * Dd + tid], acc);
        qps[tid] = acc;
    }
    __syncthreads();

    const int wrow0 = w * ROWS_PER_WARP;       // this warp's 128 rows

    uint32_t buf[2][2][16];                    // ping-pong A fragments
    load_tile(buf[0], Kc, wrow0, g, c);

    #pragma unroll 2
    for (int t = 0; t < NTILE; t++) {
        const int cur = t & 1;
        if (t + 1 < NTILE)
            load_tile(buf[cur ^ 1], Kc, wrow0 + (t + 1) * TILE_ROWS, g, c);

        // convert current tile in place (raw fp32 -> tf32 rna)
        #pragma unroll
        for (int hf = 0; hf < 2; hf++)
            #pragma unroll
            for (int i = 0; i < 16; i++)
                buf[cur][hf][i] = f2tf(__uint_as_float(buf[cur][hf][i]));

        float psum[2] = {0.f, 0.f};

        #pragma unroll
        for (int nt = 0; nt < 8; nt++) {
            const float qp0 = qps[nt * 8 + 2 * c], qp1 = qps[nt * 8 + 2 * c + 1];
            const float w0  = wos[nt * 8 + 2 * c], w1  = wos[nt * 8 + 2 * c + 1];

            float acc[4] = {0.f, 0.f, 0.f, 0.f};
            #pragma unroll
            for (int s = 0; s < 8; s++) {
                const uint2 b = Bp[(nt * 8 + s) * 32 + lane];
                mma_tf32(acc, buf[cur][0][2 * s], buf[cur][1][2 * s],
                              buf[cur][0][2 * s + 1], buf[cur][1][2 * s + 1], b.x, b.y);
            }
            psum[0] += fmaxf(acc[0] + qp0, 0.f) * w0 + fmaxf(acc[1] + qp1, 0.f) * w1;
            psum[1] += fmaxf(acc[2] + qp0, 0.f) * w0 + fmaxf(acc[3] + qp1, 0.f) * w1;
        }

        // reduce over the 4 lanes of each group, store rows g and g+8
        #pragma unroll
        for (int hf = 0; hf < 2; hf++) {
            float p = psum[hf];
            p += __shfl_xor_sync(0xffffffffu, p, 1);
            p += __shfl_xor_sync(0xffffffffu, p, 2);
            if (c == 0)
                outp[wrow0 + t * TILE_ROWS + hf * 8 + g] = p;
        }
    }
}

extern "C" void kernel_launch(void* const* d_in, const int* in_sizes, int n_in,
                              void* d_out, int out_size)
{
    const float* Q    = (const float*)d_in[0];
    const float* K    = (const float*)d_in[1];
    const float* Wc   = (const float*)d_in[2];
    const float* Wo   = (const float*)d_in[3];
    const float* bias = (const float*)d_in[4];
    float* out = (float*)d_out;

    const int grid = Bc * Hc * (KL / KCHUNK);   // 2048 blocks
    nais_mma_kernel<<<grid, NTHREADS>>>(Q, K, Wc, Wo, bias, out);
}

// round 6
// speedup vs baseline: 1.1683x; 1.1683x over previous
#include <cuda_runtime.h>
#include <cstdint>

// NAIS scoring via warp-level tf32 mma.sync with fine-grained k-slice streaming.
//
//   qp[d]  = bias[h,d] + sum_e Q[b,h,e] * Wc[h,e,d]            (fp32, exact)
//   out[k] = sum_d relu( qp[d] + (K[k,:] @ Wk)[d] ) * Wo[h,d]  (K@Wk in tf32)
//
// m16n8k8 fragments (g = lane>>2, c = lane&3):
//   A: a0=(g,s0) a1=(g+8,s0) a2=(g,s1) a3=(g+8,s1);  B: b0=(s0,n=g) b1=(s1,n=g)
//   C: c0=(g,2c) c1=(g,2c+1) c2=(g+8,2c) c3=(g+8,2c+1)
// k-slot -> physical column permutation (same for A and B), step s:
//   (c,slot0) -> 16c+2s, (c,slot1) -> 16c+2s+1
// One "slice" q = float4 at col 16c+4q = k-steps {2q, 2q+1}.
//
// Pipeline: acc[8][4] persists across the 4 slices of a 16-row tile; slice q
// computes (16 mma) while slices q+1, q+2 are in flight (ring of 4 uint4x2
// buffers, slot = q statically). Live regs ~95 -> no spill under the 128 cap
// (R5's full-tile ping-pong spilled at 128 and regressed).

namespace {
constexpr int Bc = 32, Hc = 8, KL = 8192, Dd = 64;
constexpr int NTHREADS = 256;                 // 8 warps
constexpr int KCHUNK   = 1024;                // rows per block
constexpr int ROWS_PER_WARP = KCHUNK / 8;     // 128
constexpr int TILE_ROWS = 16;
constexpr int NTILE     = ROWS_PER_WARP / TILE_ROWS;  // 8
}

__device__ __forceinline__ uint32_t f2tf(float f) {
    uint32_t r;
    asm("cvt.rna.tf32.f32 %0, %1;" : "=r"(r) : "f"(f));
    return r;
}

__device__ __forceinline__ void mma_tf32(float c[4],
                                         uint32_t a0, uint32_t a1, uint32_t a2, uint32_t a3,
                                         uint32_t b0, uint32_t b1) {
    asm volatile(
        "mma.sync.aligned.m16n8k8.row.col.f32.tf32.tf32.f32 "
        "{%0,%1,%2,%3}, {%4,%5,%6,%7}, {%8,%9}, {%0,%1,%2,%3};"
        : "+f"(c[0]), "+f"(c[1]), "+f"(c[2]), "+f"(c[3])
        : "r"(a0), "r"(a1), "r"(a2), "r"(a3), "r"(b0), "r"(b1));
}

__global__ void __launch_bounds__(NTHREADS, 2)
nais_mma_kernel(const float* __restrict__ Q, const float* __restrict__ K,
                const float* __restrict__ Wc, const float* __restrict__ Wo,
                const float* __restrict__ bias, float* __restrict__ out)
{
    // Bp[(nt*8 + s)*32 + lane] = { tf32 Wk[16c+2s][n], tf32 Wk[16c+2s+1][n] }, n = nt*8 + g
    __shared__ uint2 Bp[8 * 8 * 32];          // 16 KB
    __shared__ float qps[Dd], wos[Dd];

    const int tid  = threadIdx.x;
    const int w    = tid >> 5;
    const int lane = tid & 31;
    const int c    = lane & 3;
    const int g    = lane >> 2;

    const int bid   = blockIdx.x;
    const int bh    = bid >> 3;               // b*H + h
    const int chunk = bid & 7;
    const int h     = bh & (Hc - 1);

    const float* __restrict__ WcH = Wc + (size_t)h * 2 * Dd * Dd;
    const float* __restrict__ Wk  = WcH + Dd * Dd;
    const float* __restrict__ Kc  = K + (size_t)bh * KL * Dd + (size_t)chunk * KCHUNK * Dd;
    float* __restrict__ outp = out + (size_t)bh * KL + (size_t)chunk * KCHUNK;

    // ---- prologue ----
    #pragma unroll
    for (int i = 0; i < (8 * 8 * 32) / NTHREADS; i++) {
        int idx = tid + i * NTHREADS;          // ((nt*8 + s)*32 + ln)
        int ln = idx & 31, s = (idx >> 5) & 7, nt = idx >> 8;
        int cc = ln & 3, gg = ln >> 2;
        int e0 = 16 * cc + 2 * s;
        int n  = nt * 8 + gg;
        Bp[idx] = make_uint2(f2tf(Wk[e0 * Dd + n]), f2tf(Wk[(e0 + 1) * Dd + n]));
    }
    if (tid < Dd) {
        wos[tid] = Wo[h * Dd + tid];
        float acc = bias[h * Dd + tid];
        const float* __restrict__ q = Q + (size_t)bh * Dd;
        #pragma unroll 8
        for (int e = 0; e < Dd; e++) acc = fmaf(q[e], WcH[e * Dd + tid], acc);
        qps[tid] = acc;
    }
    __syncthreads();

    const int wrow0 = w * ROWS_PER_WARP;
    // per-thread base: row (wrow0 + g), col 16c
    const float* __restrict__ tbase = Kc + (size_t)(wrow0 + g) * Dd + 16 * c;

    uint4 Abuf[4][2];                          // ring: slot = global slice index & 3

    // load_slice(slot, t, q): rows t*16 + {g, 8+g}, cols [16c+4q, +4)
    #define LOAD_SLICE(slot, t_, q_) do {                                          \
        int tt = (t_) < NTILE ? (t_) : (NTILE - 1);                                \
        const float* _p = tbase + (size_t)(tt * TILE_ROWS) * Dd + 4 * (q_);        \
        Abuf[slot][0] = *reinterpret_cast<const uint4*>(_p);                       \
        Abuf[slot][1] = *reinterpret_cast<const uint4*>(_p + 8 * Dd);              \
    } while (0)

    LOAD_SLICE(0, 0, 0);
    LOAD_SLICE(1, 0, 1);

    for (int t = 0; t < NTILE; t++) {
        float acc[8][4];
        #pragma unroll
        for (int nt = 0; nt < 8; nt++)
            #pragma unroll
            for (int i = 0; i < 4; i++) acc[nt][i] = 0.f;

        #pragma unroll
        for (int q = 0; q < 4; q++) {
            // prefetch slice (t*4 + q + 2) into ring slot (q+2)&3
            LOAD_SLICE((q + 2) & 3, t + ((q + 2) >> 2), (q + 2) & 3);

            // convert current slice q (slot q): x,y = step 2q slots 0/1; z,w = step 2q+1
            uint32_t a[2][4];
            #pragma unroll
            for (int hf = 0; hf < 2; hf++) {
                a[hf][0] = f2tf(__uint_as_float(Abuf[q][hf].x));
                a[hf][1] = f2tf(__uint_as_float(Abuf[q][hf].y));
                a[hf][2] = f2tf(__uint_as_float(Abuf[q][hf].z));
                a[hf][3] = f2tf(__uint_as_float(Abuf[q][hf].w));
            }

            #pragma unroll
            for (int nt = 0; nt < 8; nt++) {
                const uint2 b0 = Bp[(nt * 8 + 2 * q) * 32 + lane];
                const uint2 b1 = Bp[(nt * 8 + 2 * q + 1) * 32 + lane];
                mma_tf32(acc[nt], a[0][0], a[1][0], a[0][1], a[1][1], b0.x, b0.y);
                mma_tf32(acc[nt], a[0][2], a[1][2], a[0][3], a[1][3], b1.x, b1.y);
            }
        }

        // ---- fused epilogue: relu(acc + qp) . wo, 4-lane reduce, store ----
        float psum[2] = {0.f, 0.f};
        #pragma unroll
        for (int nt = 0; nt < 8; nt++) {
            const float qp0 = qps[nt * 8 + 2 * c], qp1 = qps[nt * 8 + 2 * c + 1];
            const float w0  = wos[nt * 8 + 2 * c], w1  = wos[nt * 8 + 2 * c + 1];
            psum[0] += fmaxf(acc[nt][0] + qp0, 0.f) * w0 + fmaxf(acc[nt][1] + qp1, 0.f) * w1;
            psum[1] += fmaxf(acc[nt][2] + qp0, 0.f) * w0 + fmaxf(acc[nt][3] + qp1, 0.f) * w1;
        }
        #pragma unroll
        for (int hf = 0; hf < 2; hf++) {
            float p = psum[hf];
            p += __shfl_xor_sync(0xffffffffu, p, 1);
            p += __shfl_xor_sync(0xffffffffu, p, 2);
            if (c == 0)
                outp[wrow0 + t * TILE_ROWS + hf * 8 + g] = p;
        }
    }
    #undef LOAD_SLICE
}

extern "C" void kernel_launch(void* const* d_in, const int* in_sizes, int n_in,
                              void* d_out, int out_size)
{
    const float* Q    = (const float*)d_in[0];
    const float* K    = (const float*)d_in[1];
    const float* Wc   = (const float*)d_in[2];
    const float* Wo   = (const float*)d_in[3];
    const float* bias = (const float*)d_in[4];
    float* out = (float*)d_out;

    const int grid = Bc * Hc * (KL / KCHUNK);   // 2048 blocks
    nais_mma_kernel<<<grid, NTHREADS>>>(Q, K, Wc, Wo, bias, out);
}

// round 7
// speedup vs baseline: 1.4282x; 1.2225x over previous
#include <cuda_runtime.h>
#include <cstdint>

// NAIS scoring via warp-level tf32 mma.sync (R4 structure + line-dense loads).
//
//   qp[d]  = bias[h,d] + sum_e Q[b,h,e] * Wc[h,e,d]            (fp32, exact)
//   out[k] = sum_d relu( qp[d] + (K[k,:] @ Wk)[d] ) * Wo[h,d]  (K@Wk in tf32)
//
// m16n8k8 fragments (g = lane>>2, c = lane&3):
//   A: a0=(g,s0) a1=(g+8,s0) a2=(g,s1) a3=(g+8,s1);  B: b0=(s0,n=g) b1=(s1,n=g)
//   C: c0=(g,2c) c1=(g,2c+1) c2=(g+8,2c) c3=(g+8,2c+1)
//
// Column permutation (LINE-DENSE, applied identically to A and B):
//   step s = 2j+t, thread c:  slot0 -> col 16j + 4c + 2t,  slot1 -> col +1.
//   Thread's j-th float4 = row bytes [64j+16c, +16)  =>  per LDG.128 the 4
//   lanes of a row cover one contiguous 64B chunk inside ONE 128B line:
//   8 lines/LDG instead of 16 -> L1tex wavefronts per warp-iter halve.
//   A-register indexing is unchanged vs R4: step s uses A[2s], A[2s+1].

namespace {
constexpr int Bc = 32, Hc = 8, KL = 8192, Dd = 64;
constexpr int NTHREADS = 256;                 // 8 warps
constexpr int KCHUNK   = 2048;                // rows per block
constexpr int ROWS_PER_ITER = 256;            // 8 warps x 32 rows
constexpr int NITER    = KCHUNK / ROWS_PER_ITER;  // 8
}

__device__ __forceinline__ uint32_t f2tf(float f) {
    uint32_t r;
    asm("cvt.rna.tf32.f32 %0, %1;" : "=r"(r) : "f"(f));
    return r;
}

__device__ __forceinline__ void mma_tf32(float c[4],
                                         uint32_t a0, uint32_t a1, uint32_t a2, uint32_t a3,
                                         uint32_t b0, uint32_t b1) {
    asm volatile(
        "mma.sync.aligned.m16n8k8.row.col.f32.tf32.tf32.f32 "
        "{%0,%1,%2,%3}, {%4,%5,%6,%7}, {%8,%9}, {%0,%1,%2,%3};"
        : "+f"(c[0]), "+f"(c[1]), "+f"(c[2]), "+f"(c[3])
        : "r"(a0), "r"(a1), "r"(a2), "r"(a3), "r"(b0), "r"(b1));
}

__global__ void __launch_bounds__(NTHREADS, 2)
nais_mma_kernel(const float* __restrict__ Q, const float* __restrict__ K,
                const float* __restrict__ Wc, const float* __restrict__ Wo,
                const float* __restrict__ bias, float* __restrict__ out)
{
    // Bp[(nt*8 + s)*32 + lane] = { tf32 Wk[e0][n], tf32 Wk[e0+1][n] },
    //   e0 = 16*(s>>1) + 4c + 2*(s&1),  n = nt*8 + g
    __shared__ uint2 Bp[8 * 8 * 32];          // 16 KB
    __shared__ float qps[Dd], wos[Dd];

    const int tid  = threadIdx.x;
    const int w    = tid >> 5;
    const int lane = tid & 31;
    const int c    = lane & 3;                // threadID_in_group
    const int g    = lane >> 2;               // groupID

    const int bid   = blockIdx.x;
    const int bh    = bid >> 2;               // b*H + h
    const int chunk = bid & 3;
    const int h     = bh & (Hc - 1);

    const float* __restrict__ WcH = Wc + (size_t)h * 2 * Dd * Dd;
    const float* __restrict__ Wk  = WcH + Dd * Dd;    // bottom half: [e][d]
    const float* __restrict__ Kc  = K + (size_t)bh * KL * Dd + (size_t)chunk * KCHUNK * Dd;
    float* __restrict__ outp = out + (size_t)bh * KL + (size_t)chunk * KCHUNK;

    // ---- prologue ----
    #pragma unroll
    for (int i = 0; i < (8 * 8 * 32) / NTHREADS; i++) {   // 8 packs/thread
        int idx = tid + i * NTHREADS;          // ((nt*8 + s)*32 + ln)
        int ln = idx & 31, s = (idx >> 5) & 7, nt = idx >> 8;
        int cc = ln & 3, gg = ln >> 2;
        int e0 = 16 * (s >> 1) + 4 * cc + 2 * (s & 1);   // line-dense map
        int n  = nt * 8 + gg;
        Bp[idx] = make_uint2(f2tf(Wk[e0 * Dd + n]), f2tf(Wk[(e0 + 1) * Dd + n]));
    }
    if (tid < Dd) {                            // qp = bias + Q @ Wq (fp32 exact); wo
        wos[tid] = Wo[h * Dd + tid];
        float acc = bias[h * Dd + tid];
        const float* __restrict__ q = Q + (size_t)bh * Dd;
        #pragma unroll 8
        for (int e = 0; e < Dd; e++) acc = fmaf(q[e], WcH[e * Dd + tid], acc);
        qps[tid] = acc;
    }
    __syncthreads();

    // ---- main loop: 32 rows per warp per iter, A straight from GMEM ----
    for (int it = 0; it < NITER; it++) {
        const int rowbase = it * ROWS_PER_ITER + w * 32;

        // A fragments: thread owns cols {16j+4c .. +4} (j=0..3) of rows rt*16+hf*8+g.
        // Load j-th float4 at q[4j + c] -> per-LDG line-dense.
        uint32_t A[2][2][16];
        #pragma unroll
        for (int rt = 0; rt < 2; rt++)
            #pragma unroll
            for (int hf = 0; hf < 2; hf++) {
                const int r = rowbase + rt * 16 + hf * 8 + g;
                const float4* p = reinterpret_cast<const float4*>(Kc + (size_t)r * Dd);
                float4 f0 = p[c], f1 = p[4 + c], f2 = p[8 + c], f3 = p[12 + c];
                A[rt][hf][0]  = f2tf(f0.x); A[rt][hf][1]  = f2tf(f0.y);
                A[rt][hf][2]  = f2tf(f0.z); A[rt][hf][3]  = f2tf(f0.w);
                A[rt][hf][4]  = f2tf(f1.x); A[rt][hf][5]  = f2tf(f1.y);
                A[rt][hf][6]  = f2tf(f1.z); A[rt][hf][7]  = f2tf(f1.w);
                A[rt][hf][8]  = f2tf(f2.x); A[rt][hf][9]  = f2tf(f2.y);
                A[rt][hf][10] = f2tf(f2.z); A[rt][hf][11] = f2tf(f2.w);
                A[rt][hf][12] = f2tf(f3.x); A[rt][hf][13] = f2tf(f3.y);
                A[rt][hf][14] = f2tf(f3.z); A[rt][hf][15] = f2tf(f3.w);
            }

        float psum[2][2] = {{0.f, 0.f}, {0.f, 0.f}};

        #pragma unroll
        for (int nt = 0; nt < 8; nt++) {
            const float qp0 = qps[nt * 8 + 2 * c], qp1 = qps[nt * 8 + 2 * c + 1];
            const float w0  = wos[nt * 8 + 2 * c], w1  = wos[nt * 8 + 2 * c + 1];

            float acc0[4] = {0.f, 0.f, 0.f, 0.f};
            float acc1[4] = {0.f, 0.f, 0.f, 0.f};

            #pragma unroll
            for (int s = 0; s < 8; s++) {
                const uint2 b = Bp[(nt * 8 + s) * 32 + lane];
                mma_tf32(acc0, A[0][0][2 * s], A[0][1][2 * s],
                               A[0][0][2 * s + 1], A[0][1][2 * s + 1], b.x, b.y);
                mma_tf32(acc1, A[1][0][2 * s], A[1][1][2 * s],
                               A[1][0][2 * s + 1], A[1][1][2 * s + 1], b.x, b.y);
            }
            psum[0][0] += fmaxf(acc0[0] + qp0, 0.f) * w0 + fmaxf(acc0[1] + qp1, 0.f) * w1;
            psum[0][1] += fmaxf(acc0[2] + qp0, 0.f) * w0 + fmaxf(acc0[3] + qp1, 0.f) * w1;
            psum[1][0] += fmaxf(acc1[0] + qp0, 0.f) * w0 + fmaxf(acc1[1] + qp1, 0.f) * w1;
            psum[1][1] += fmaxf(acc1[2] + qp0, 0.f) * w0 + fmaxf(acc1[3] + qp1, 0.f) * w1;
        }

        // reduce over the 4 lanes of each group (c = 0..3), then store
        #pragma unroll
        for (int rt = 0; rt < 2; rt++)
            #pragma unroll
            for (int hf = 0; hf < 2; hf++) {
                float p = psum[rt][hf];
                p += __shfl_xor_sync(0xffffffffu, p, 1);
                p += __shfl_xor_sync(0xffffffffu, p, 2);
                if (c == 0)
                    outp[rowbase + rt * 16 + hf * 8 + g] = p;
            }
    }
}

extern "C" void kernel_launch(void* const* d_in, const int* in_sizes, int n_in,
                              void* d_out, int out_size)
{
    const float* Q    = (const float*)d_in[0];
    const float* K    = (const float*)d_in[1];
    const float* Wc   = (const float*)d_in[2];
    const float* Wo   = (const float*)d_in[3];
    const float* bias = (const float*)d_in[4];
    float* out = (float*)d_out;

    const int grid = Bc * Hc * (KL / KCHUNK);   // 1024 blocks
    nais_mma_kernel<<<grid, NTHREADS>>>(Q, K, Wc, Wo, bias, out);
}